// round 1
// baseline (speedup 1.0000x reference)
#include <cuda_runtime.h>

// Problem constants (fixed shapes: B=1, C=1, H=W=96)
#define NN      9216
#define WW      96
#define INV_SXY (1.0f / 15.0f)
#define INV_SRGB 8.0f
#define LOG2E   1.4426950408889634f
#define NHL2E   (-0.7213475204444817f)   // -0.5 * log2(e)
#define LN2     0.6931471805599453f

#define TPB    256
#define IPT    4          // i's per thread
#define ITILE  (TPB * IPT)   // 1024 -> 9 i-tiles
#define JCHUNK 576           // 16 j-chunks
#define NITILE (NN / ITILE)  // 9
#define NJCHUNK (NN / JCHUNK) // 16

// Packed per-pixel features (precomputed once per launch).
// packA = {g0, g1, g2, g3}           g = log2(e) * feat
// packB = {g4, b,  t,  s }           b = -0.5*log2(e)*|feat|^2, t = 1-s
__device__ float4 g_packA[NN];
__device__ float4 g_packB[NN];

__global__ void zero_out_kernel(float* out, int n) {
    int i = blockIdx.x * blockDim.x + threadIdx.x;
    if (i < n) out[i] = 0.0f;
}

__global__ void precompute_kernel(const float* __restrict__ inp,
                                  const float* __restrict__ img) {
    int n = blockIdx.x * blockDim.x + threadIdx.x;
    if (n >= NN) return;
    float x = (float)(n % WW) * INV_SXY;
    float y = (float)(n / WW) * INV_SXY;
    float r = img[n]          * INV_SRGB;
    float g = img[NN + n]     * INV_SRGB;
    float b = img[2 * NN + n] * INV_SRGB;
    float sq = x * x + y * y + r * r + g * g + b * b;
    float s = inp[n];
    g_packA[n] = make_float4(LOG2E * x, LOG2E * y, LOG2E * r, LOG2E * g);
    g_packB[n] = make_float4(LOG2E * b, NHL2E * sq, 1.0f - s, s);
}

// Each block: i-tile (1024 i's, 4 per thread) x j-chunk (576 j's in smem).
// arg2(i,j) = a_i + b_j + f_i . g_j   where f = ln2 * g  (so f_i.g_j = -log2e*(-2 f.f)/... )
// w = 2^arg2 = exp(-0.5 * d2);  acc_i += w * (1 - s_j);  loss += s_i * acc_i / N.
__global__ __launch_bounds__(TPB, 1)
void crf_main_kernel(float* __restrict__ out) {
    __shared__ float4 sA[JCHUNK];
    __shared__ float4 sB[JCHUNK];
    __shared__ float sred[TPB / 32];

    const int t  = threadIdx.x;
    const int i0 = blockIdx.x * ITILE;
    const int j0 = blockIdx.y * JCHUNK;

    // Cooperative j-tile load (already in scaled g/b/t format)
    for (int k = t; k < JCHUNK; k += TPB) {
        sA[k] = g_packA[j0 + k];
        sB[k] = g_packB[j0 + k];
    }

    // Per-thread i registers
    float f0[IPT], f1[IPT], f2[IPT], f3[IPT], f4[IPT];
    float a[IPT], si[IPT], acc[IPT];
#pragma unroll
    for (int u = 0; u < IPT; u++) {
        int i = i0 + u * TPB + t;       // coalesced
        float4 A  = g_packA[i];
        float4 Bv = g_packB[i];
        f0[u] = LN2 * A.x;  f1[u] = LN2 * A.y;  f2[u] = LN2 * A.z;
        f3[u] = LN2 * A.w;  f4[u] = LN2 * Bv.x;
        a[u]  = Bv.y;  si[u] = Bv.w;  acc[u] = 0.0f;
    }
    __syncthreads();

    for (int jj = 0; jj < JCHUNK; jj++) {
        float4 A  = sA[jj];   // g0..g3  (broadcast LDS.128)
        float4 Bv = sB[jj];   // g4, b_j, t_j, s_j
#pragma unroll
        for (int u = 0; u < IPT; u++) {
            float arg = a[u] + Bv.y;
            arg = fmaf(f0[u], A.x,  arg);
            arg = fmaf(f1[u], A.y,  arg);
            arg = fmaf(f2[u], A.z,  arg);
            arg = fmaf(f3[u], A.w,  arg);
            arg = fmaf(f4[u], Bv.x, arg);
            float w;
            asm("ex2.approx.ftz.f32 %0, %1;" : "=f"(w) : "f"(arg));
            acc[u] = fmaf(w, Bv.z, acc[u]);
        }
    }

    // thread total: sum_u s_i * acc_i, pre-scaled by 1/N
    float tot = 0.0f;
#pragma unroll
    for (int u = 0; u < IPT; u++) tot = fmaf(si[u], acc[u], tot);
    tot *= (1.0f / (float)NN);

    // block reduce: warp shuffle then smem
#pragma unroll
    for (int off = 16; off > 0; off >>= 1)
        tot += __shfl_xor_sync(0xFFFFFFFFu, tot, off);
    if ((t & 31) == 0) sred[t >> 5] = tot;
    __syncthreads();
    if (t < 32) {
        float v = (t < TPB / 32) ? sred[t] : 0.0f;
#pragma unroll
        for (int off = 4; off > 0; off >>= 1)
            v += __shfl_xor_sync(0xFFFFFFFFu, v, off);
        if (t == 0) atomicAdd(out, v);
    }
}

extern "C" void kernel_launch(void* const* d_in, const int* in_sizes, int n_in,
                              void* d_out, int out_size) {
    const float* inp = (const float*)d_in[0];   // [1,1,96,96] seg probs
    const float* img = (const float*)d_in[1];   // [1,3,96,96] rgb
    float* out = (float*)d_out;

    zero_out_kernel<<<1, 32>>>(out, out_size);
    precompute_kernel<<<(NN + 255) / 256, 256>>>(inp, img);
    dim3 grid(NITILE, NJCHUNK);
    crf_main_kernel<<<grid, TPB>>>(out);
}

// round 2
// speedup vs baseline: 1.2039x; 1.2039x over previous
#include <cuda_runtime.h>

// Problem constants (fixed shapes: B=1, C=1, H=W=96)
#define NN       9216
#define WW       96
#define INV_SXY  (1.0f / 15.0f)
#define INV_SRGB 8.0f
#define LOG2E    1.4426950408889634f
#define NHL2E    (-0.7213475204444817f)   // -0.5 * log2(e)
#define LN2      0.6931471805599453f

// Triangular tiling: 16x16 grid of 576x576 tiles -> 136 upper-triangle blocks
#define NB     16
#define TILE   576            // NN / NB
#define TPB    192
#define IPT    3              // TPB * IPT == TILE
#define NBLOCKS (NB * (NB + 1) / 2)   // 136

// Packed per-pixel features (precomputed once per launch sequence).
// packA = {g0, g1, g2, g3}        g = log2(e) * feat
// packB = {g4, b,  t,  s }        b = -0.5*log2(e)*|feat|^2, t = 1-s
__device__ float4 g_packA[NN];
__device__ float4 g_packB[NN];

__global__ void precompute_kernel(const float* __restrict__ inp,
                                  const float* __restrict__ img,
                                  float* __restrict__ out, int out_size) {
    int n = blockIdx.x * blockDim.x + threadIdx.x;
    if (n < out_size) out[n] = 0.0f;           // fused output zeroing
    if (n >= NN) return;
    float x = (float)(n % WW) * INV_SXY;
    float y = (float)(n / WW) * INV_SXY;
    float r = img[n]          * INV_SRGB;
    float g = img[NN + n]     * INV_SRGB;
    float b = img[2 * NN + n] * INV_SRGB;
    float sq = x * x + y * y + r * r + g * g + b * b;
    float s = inp[n];
    g_packA[n] = make_float4(LOG2E * x, LOG2E * y, LOG2E * r, LOG2E * g);
    g_packB[n] = make_float4(LOG2E * b, NHL2E * sq, 1.0f - s, s);
}

// Triangular-symmetric dense CRF loss.
//   w_ij = exp(-0.5*d2) = 2^(a_i + b_j + f_i.g_j)
// Diagonal blocks (bi==bj): standard  sum_i s_i * sum_j w*(1-s_j)   (full tile,
//   both orders counted by the loop itself).
// Off-diagonal blocks (bi<bj): each unordered cross pair counted once with the
//   symmetric coefficient c = s_i(1-s_j) + s_j(1-s_i) = fmaf(s_i, 1-2*s_j, s_j).
__global__ __launch_bounds__(TPB, 1)
void crf_main_kernel(float* __restrict__ out) {
    __shared__ float4 sA[TILE];
    __shared__ float4 sB[TILE];
    __shared__ float  sred[TPB / 32];

    // Decode upper-triangle block index -> (bi, bj), bi <= bj
    int b  = blockIdx.x;
    int bi = 0;
    while (b >= NB - bi) { b -= NB - bi; bi++; }
    int bj = bi + b;

    const int t  = threadIdx.x;
    const int i0 = bi * TILE;
    const int j0 = bj * TILE;

    // Cooperative j-tile load into shared
    for (int k = t; k < TILE; k += TPB) {
        sA[k] = g_packA[j0 + k];
        sB[k] = g_packB[j0 + k];
    }

    // Per-thread i registers (f = ln2 * g so that f_i.g_j gives the log2-domain dot)
    float f0[IPT], f1[IPT], f2[IPT], f3[IPT], f4[IPT];
    float a[IPT], si[IPT], acc[IPT];
#pragma unroll
    for (int u = 0; u < IPT; u++) {
        int i = i0 + u * TPB + t;           // coalesced
        float4 A  = g_packA[i];
        float4 Bv = g_packB[i];
        f0[u] = LN2 * A.x;  f1[u] = LN2 * A.y;  f2[u] = LN2 * A.z;
        f3[u] = LN2 * A.w;  f4[u] = LN2 * Bv.x;
        a[u]  = Bv.y;  si[u] = Bv.w;  acc[u] = 0.0f;
    }
    __syncthreads();

    float tot = 0.0f;
    if (bi == bj) {
        for (int jj = 0; jj < TILE; jj++) {
            float4 A  = sA[jj];             // broadcast LDS.128
            float4 Bv = sB[jj];
#pragma unroll
            for (int u = 0; u < IPT; u++) {
                float arg = a[u] + Bv.y;
                arg = fmaf(f0[u], A.x,  arg);
                arg = fmaf(f1[u], A.y,  arg);
                arg = fmaf(f2[u], A.z,  arg);
                arg = fmaf(f3[u], A.w,  arg);
                arg = fmaf(f4[u], Bv.x, arg);
                float w;
                asm("ex2.approx.ftz.f32 %0, %1;" : "=f"(w) : "f"(arg));
                acc[u] = fmaf(w, Bv.z, acc[u]);     // += w * (1 - s_j)
            }
        }
#pragma unroll
        for (int u = 0; u < IPT; u++) tot = fmaf(si[u], acc[u], tot);
    } else {
        for (int jj = 0; jj < TILE; jj++) {
            float4 A  = sA[jj];
            float4 Bv = sB[jj];
            float p = fmaf(-2.0f, Bv.w, 1.0f);      // 1 - 2*s_j  (amortized over IPT)
#pragma unroll
            for (int u = 0; u < IPT; u++) {
                float arg = a[u] + Bv.y;
                arg = fmaf(f0[u], A.x,  arg);
                arg = fmaf(f1[u], A.y,  arg);
                arg = fmaf(f2[u], A.z,  arg);
                arg = fmaf(f3[u], A.w,  arg);
                arg = fmaf(f4[u], Bv.x, arg);
                float w;
                asm("ex2.approx.ftz.f32 %0, %1;" : "=f"(w) : "f"(arg));
                float c = fmaf(si[u], p, Bv.w);     // s_i + s_j - 2 s_i s_j
                acc[u] = fmaf(w, c, acc[u]);
            }
        }
#pragma unroll
        for (int u = 0; u < IPT; u++) tot += acc[u];   // both orders already included
    }

    tot *= (1.0f / (float)NN);

    // Block reduce: warp shuffle then smem
#pragma unroll
    for (int off = 16; off > 0; off >>= 1)
        tot += __shfl_xor_sync(0xFFFFFFFFu, tot, off);
    if ((t & 31) == 0) sred[t >> 5] = tot;
    __syncthreads();
    if (t < 32) {
        float v = (t < TPB / 32) ? sred[t] : 0.0f;
#pragma unroll
        for (int off = 4; off > 0; off >>= 1)
            v += __shfl_xor_sync(0xFFFFFFFFu, v, off);
        if (t == 0) atomicAdd(out, v);
    }
}

extern "C" void kernel_launch(void* const* d_in, const int* in_sizes, int n_in,
                              void* d_out, int out_size) {
    const float* inp = (const float*)d_in[0];   // [1,1,96,96] seg probs
    const float* img = (const float*)d_in[1];   // [1,3,96,96] rgb
    float* out = (float*)d_out;

    precompute_kernel<<<(NN + 255) / 256, 256>>>(inp, img, out, out_size);
    crf_main_kernel<<<NBLOCKS, TPB>>>(out);
}

// round 3
// speedup vs baseline: 1.5878x; 1.3189x over previous
#include <cuda_runtime.h>

// Problem constants (fixed shapes: B=1, C=1, H=W=96)
#define NN       9216
#define WW       96
#define INV_SXY  (1.0f / 15.0f)
#define INV_SRGB 8.0f
#define LOG2E    1.4426950408889634f
#define NHL2E    (-0.7213475204444817f)   // -0.5 * log2(e)
#define LN2      0.6931471805599453f

// Triangular tiling: 24x24 grid of 384x384 tiles -> 300 upper-triangle blocks
#define NB      24
#define TILE    384            // NN / NB
#define NPAIR   (TILE / 2)     // 192 j-pairs per tile
#define TPB     128
#define IPT     3              // TPB * IPT == TILE
#define NBLOCKS (NB * (NB + 1) / 2)   // 300

// ---- f32x2 helpers (sm_103a packed fp32 pipe; ptxas won't auto-fuse) ----
typedef unsigned long long u64;
__device__ __forceinline__ u64 pack2(float lo, float hi) {
    u64 r; asm("mov.b64 %0, {%1,%2};" : "=l"(r) : "f"(lo), "f"(hi)); return r;
}
__device__ __forceinline__ void unpack2(u64 v, float& lo, float& hi) {
    asm("mov.b64 {%0,%1}, %2;" : "=f"(lo), "=f"(hi) : "l"(v));
}
__device__ __forceinline__ u64 fma2(u64 a, u64 b, u64 c) {
    u64 r; asm("fma.rn.f32x2 %0, %1, %2, %3;" : "=l"(r) : "l"(a), "l"(b), "l"(c)); return r;
}
__device__ __forceinline__ u64 add2(u64 a, u64 b) {
    u64 r; asm("add.rn.f32x2 %0, %1, %2;" : "=l"(r) : "l"(a), "l"(b)); return r;
}

// Scalar per-pixel features (for the i-side loads)
// packA = {g0, g1, g2, g3}   g = log2(e) * feat
// packB = {g4, b,  t,  s }   b = -0.5*log2(e)*|f|^2, t = 1-s
__device__ float4 g_packA[NN];
__device__ float4 g_packB[NN];
// Pair-packed j-side features: pair p covers pixels (2p, 2p+1)
// pair0 = {g0_0,g0_1, g1_0,g1_1}   pair1 = {g2_0,g2_1, g3_0,g3_1}
// pair2 = {g4_0,g4_1, b_0, b_1}    pair3 = {t_0, t_1,  s_0, s_1}
__device__ float4 g_pair0[NN / 2];
__device__ float4 g_pair1[NN / 2];
__device__ float4 g_pair2[NN / 2];
__device__ float4 g_pair3[NN / 2];

__global__ void precompute_kernel(const float* __restrict__ inp,
                                  const float* __restrict__ img,
                                  float* __restrict__ out, int out_size) {
    int p = blockIdx.x * blockDim.x + threadIdx.x;
    if (p < out_size) out[p] = 0.0f;           // fused output zeroing
    if (p >= NN / 2) return;
    float g0[2], g1[2], g2[2], g3[2], g4[2], bb[2], tt[2], ss[2];
#pragma unroll
    for (int l = 0; l < 2; l++) {
        int n = 2 * p + l;
        float x = (float)(n % WW) * INV_SXY;
        float y = (float)(n / WW) * INV_SXY;
        float r = img[n]          * INV_SRGB;
        float g = img[NN + n]     * INV_SRGB;
        float b = img[2 * NN + n] * INV_SRGB;
        float sq = x * x + y * y + r * r + g * g + b * b;
        float s = inp[n];
        g0[l] = LOG2E * x;  g1[l] = LOG2E * y;  g2[l] = LOG2E * r;
        g3[l] = LOG2E * g;  g4[l] = LOG2E * b;
        bb[l] = NHL2E * sq; tt[l] = 1.0f - s;   ss[l] = s;
        g_packA[n] = make_float4(g0[l], g1[l], g2[l], g3[l]);
        g_packB[n] = make_float4(g4[l], bb[l], tt[l], ss[l]);
    }
    g_pair0[p] = make_float4(g0[0], g0[1], g1[0], g1[1]);
    g_pair1[p] = make_float4(g2[0], g2[1], g3[0], g3[1]);
    g_pair2[p] = make_float4(g4[0], g4[1], bb[0], bb[1]);
    g_pair3[p] = make_float4(tt[0], tt[1], ss[0], ss[1]);
}

// Triangular-symmetric dense CRF loss with f32x2 lane-pairing over j.
//   w_ij = 2^(a_i + b_j + f_i.g_j) = exp(-0.5*d2)
// Diagonal blocks:   acc += w * (1-s_j), then * s_i
// Off-diag blocks:   acc += w * (s_i + s_j - 2 s_i s_j)   (covers both orders)
__global__ __launch_bounds__(TPB)
void crf_main_kernel(float* __restrict__ out) {
    __shared__ float4 sP0[NPAIR], sP1[NPAIR], sP2[NPAIR], sP3[NPAIR];
    __shared__ float  sred[TPB / 32];

    // Decode upper-triangle block index -> (bi, bj), bi <= bj
    int b  = blockIdx.x;
    int bi = 0;
    while (b >= NB - bi) { b -= NB - bi; bi++; }
    int bj = bi + b;

    const int t  = threadIdx.x;
    const int i0 = bi * TILE;
    const int p0 = bj * NPAIR;      // j-pair base

    for (int k = t; k < NPAIR; k += TPB) {
        sP0[k] = g_pair0[p0 + k];
        sP1[k] = g_pair1[p0 + k];
        sP2[k] = g_pair2[p0 + k];
        sP3[k] = g_pair3[p0 + k];
    }

    // Per-thread i registers, broadcast-packed (loop-invariant)
    u64 F0[IPT], F1[IPT], F2[IPT], F3[IPT], F4[IPT], A2[IPT], SI2[IPT], ACC[IPT];
    float si[IPT];
#pragma unroll
    for (int u = 0; u < IPT; u++) {
        int i = i0 + u * TPB + t;           // coalesced
        float4 A  = g_packA[i];
        float4 Bv = g_packB[i];
        F0[u] = pack2(LN2 * A.x,  LN2 * A.x);
        F1[u] = pack2(LN2 * A.y,  LN2 * A.y);
        F2[u] = pack2(LN2 * A.z,  LN2 * A.z);
        F3[u] = pack2(LN2 * A.w,  LN2 * A.w);
        F4[u] = pack2(LN2 * Bv.x, LN2 * Bv.x);
        A2[u] = pack2(Bv.y, Bv.y);
        SI2[u] = pack2(Bv.w, Bv.w);
        si[u] = Bv.w;
        ACC[u] = 0ull;
    }
    __syncthreads();

    const u64 NEG2 = pack2(-2.0f, -2.0f);
    const u64 ONE2 = pack2(1.0f, 1.0f);
    float tot = 0.0f;

    if (bi == bj) {
#pragma unroll 2
        for (int jj = 0; jj < NPAIR; jj++) {
            float4 P0 = sP0[jj], P1 = sP1[jj], P2 = sP2[jj], P3 = sP3[jj];
            u64 G0 = pack2(P0.x, P0.y), G1 = pack2(P0.z, P0.w);
            u64 G2 = pack2(P1.x, P1.y), G3 = pack2(P1.z, P1.w);
            u64 G4 = pack2(P2.x, P2.y), B2 = pack2(P2.z, P2.w);
            u64 T2 = pack2(P3.x, P3.y);
#pragma unroll
            for (int u = 0; u < IPT; u++) {
                u64 arg = add2(A2[u], B2);
                arg = fma2(F0[u], G0, arg);
                arg = fma2(F1[u], G1, arg);
                arg = fma2(F2[u], G2, arg);
                arg = fma2(F3[u], G3, arg);
                arg = fma2(F4[u], G4, arg);
                float a0, a1, w0, w1;
                unpack2(arg, a0, a1);
                asm("ex2.approx.ftz.f32 %0, %1;" : "=f"(w0) : "f"(a0));
                asm("ex2.approx.ftz.f32 %0, %1;" : "=f"(w1) : "f"(a1));
                ACC[u] = fma2(pack2(w0, w1), T2, ACC[u]);   // += w * (1-s_j)
            }
        }
#pragma unroll
        for (int u = 0; u < IPT; u++) {
            float lo, hi; unpack2(ACC[u], lo, hi);
            tot = fmaf(si[u], lo + hi, tot);
        }
    } else {
#pragma unroll 2
        for (int jj = 0; jj < NPAIR; jj++) {
            float4 P0 = sP0[jj], P1 = sP1[jj], P2 = sP2[jj], P3 = sP3[jj];
            u64 G0 = pack2(P0.x, P0.y), G1 = pack2(P0.z, P0.w);
            u64 G2 = pack2(P1.x, P1.y), G3 = pack2(P1.z, P1.w);
            u64 G4 = pack2(P2.x, P2.y), B2 = pack2(P2.z, P2.w);
            u64 S2 = pack2(P3.z, P3.w);
            u64 Pc = fma2(S2, NEG2, ONE2);                  // 1 - 2*s_j
#pragma unroll
            for (int u = 0; u < IPT; u++) {
                u64 arg = add2(A2[u], B2);
                arg = fma2(F0[u], G0, arg);
                arg = fma2(F1[u], G1, arg);
                arg = fma2(F2[u], G2, arg);
                arg = fma2(F3[u], G3, arg);
                arg = fma2(F4[u], G4, arg);
                float a0, a1, w0, w1;
                unpack2(arg, a0, a1);
                asm("ex2.approx.ftz.f32 %0, %1;" : "=f"(w0) : "f"(a0));
                asm("ex2.approx.ftz.f32 %0, %1;" : "=f"(w1) : "f"(a1));
                u64 C2 = fma2(SI2[u], Pc, S2);              // s_i + s_j - 2 s_i s_j
                ACC[u] = fma2(pack2(w0, w1), C2, ACC[u]);
            }
        }
#pragma unroll
        for (int u = 0; u < IPT; u++) {
            float lo, hi; unpack2(ACC[u], lo, hi);
            tot += lo + hi;                                  // both orders included
        }
    }

    tot *= (1.0f / (float)NN);

    // Block reduce: warp shuffle then smem
#pragma unroll
    for (int off = 16; off > 0; off >>= 1)
        tot += __shfl_xor_sync(0xFFFFFFFFu, tot, off);
    if ((t & 31) == 0) sred[t >> 5] = tot;
    __syncthreads();
    if (t < 32) {
        float v = (t < TPB / 32) ? sred[t] : 0.0f;
#pragma unroll
        for (int off = 4; off > 0; off >>= 1)
            v += __shfl_xor_sync(0xFFFFFFFFu, v, off);
        if (t == 0) atomicAdd(out, v);
    }
}

extern "C" void kernel_launch(void* const* d_in, const int* in_sizes, int n_in,
                              void* d_out, int out_size) {
    const float* inp = (const float*)d_in[0];   // [1,1,96,96] seg probs
    const float* img = (const float*)d_in[1];   // [1,3,96,96] rgb
    float* out = (float*)d_out;

    precompute_kernel<<<(NN / 2 + 255) / 256, 256>>>(inp, img, out, out_size);
    crf_main_kernel<<<NBLOCKS, TPB>>>(out);
}